// round 1
// baseline (speedup 1.0000x reference)
#include <cuda_runtime.h>
#include <math.h>

// Problem constants
constexpr int BN = 4;
constexpr int NF = 64;
constexpr int H  = 128;
constexpr int W  = 128;
constexpr int HW = H * W;
constexpr int K  = 9;

// Scratch (device globals: no runtime allocation allowed)
__device__ float g_bufA[BN * NF * HW];
__device__ float g_bufB[BN * NF * HW];

__device__ __forceinline__ float lrelu(float v) { return v >= 0.f ? v : 0.1f * v; }

// ---------------------------------------------------------------------------
// 3x3 conv + leaky ReLU. Block: 256 threads = 32 x-groups (4 px each) x 8 rows.
// Tile: 8 rows x full width (128) x COB output channels. Weights in smem,
// read as warp-uniform broadcasts. Each thread: 4 px x COB accumulators.
// Grid: (H/8, CO/COB, B)
// ---------------------------------------------------------------------------
template <int CI, int CO, int COB, bool CONCAT>
__global__ __launch_bounds__(256)
void conv3x3_lrelu_kernel(const float* __restrict__ inA, const float* __restrict__ inB,
                          const float* __restrict__ w, const float* __restrict__ bias,
                          float* __restrict__ out)
{
    __shared__ float sw[COB * CI * 9];
    const int t   = threadIdx.x;
    const int cog = blockIdx.y;
    const int b   = blockIdx.z;

    const float* wsrc = w + (size_t)cog * COB * CI * 9;
    for (int i = t; i < COB * CI * 9; i += 256) sw[i] = wsrc[i];
    __syncthreads();

    const int tx = t & 31, ty = t >> 5;
    const int y  = blockIdx.x * 8 + ty;
    const int x0 = tx * 4;

    float acc[COB][4];
#pragma unroll
    for (int o = 0; o < COB; o++)
#pragma unroll
        for (int p = 0; p < 4; p++) acc[o][p] = 0.f;

    const bool vt = (y > 0), vb = (y < H - 1), vl = (x0 > 0), vr = (x0 + 4 < W);

    for (int ci = 0; ci < CI; ci++) {
        const float* p;
        if (CONCAT)
            p = (ci < NF) ? (inA + ((size_t)b * NF + ci) * HW)
                          : (inB + ((size_t)b * NF + (ci - NF)) * HW);
        else
            p = inA + ((size_t)b * CI + ci) * HW;

        float r[3][6];
        {   // row y (always valid)
            const float* rp = p + y * W;
            float4 v = *(const float4*)(rp + x0);
            r[1][1] = v.x; r[1][2] = v.y; r[1][3] = v.z; r[1][4] = v.w;
            r[1][0] = vl ? rp[x0 - 1] : 0.f;
            r[1][5] = vr ? rp[x0 + 4] : 0.f;
        }
        {   // row y-1
            const float* rp = p + (y - 1) * W;
            float4 v = vt ? *(const float4*)(rp + x0) : make_float4(0.f, 0.f, 0.f, 0.f);
            r[0][1] = v.x; r[0][2] = v.y; r[0][3] = v.z; r[0][4] = v.w;
            r[0][0] = (vt && vl) ? rp[x0 - 1] : 0.f;
            r[0][5] = (vt && vr) ? rp[x0 + 4] : 0.f;
        }
        {   // row y+1
            const float* rp = p + (y + 1) * W;
            float4 v = vb ? *(const float4*)(rp + x0) : make_float4(0.f, 0.f, 0.f, 0.f);
            r[2][1] = v.x; r[2][2] = v.y; r[2][3] = v.z; r[2][4] = v.w;
            r[2][0] = (vb && vl) ? rp[x0 - 1] : 0.f;
            r[2][5] = (vb && vr) ? rp[x0 + 4] : 0.f;
        }

        const float* wci = sw + ci * 9;
#pragma unroll
        for (int tap = 0; tap < 9; tap++) {
            const int dy = tap / 3, dx = tap - dy * 3;
            float wv[COB];
#pragma unroll
            for (int o = 0; o < COB; o++) wv[o] = wci[o * (CI * 9) + tap];
#pragma unroll
            for (int px = 0; px < 4; px++) {
                const float xv = r[dy][px + dx];
#pragma unroll
                for (int o = 0; o < COB; o++) acc[o][px] = fmaf(xv, wv[o], acc[o][px]);
            }
        }
    }

#pragma unroll
    for (int o = 0; o < COB; o++) {
        const int co = cog * COB + o;
        const float bb = bias[co];
        float4 v;
        v.x = lrelu(acc[o][0] + bb);
        v.y = lrelu(acc[o][1] + bb);
        v.z = lrelu(acc[o][2] + bb);
        v.w = lrelu(acc[o][3] + bb);
        *(float4*)(out + ((size_t)b * CO + co) * HW + y * W + x0) = v;
    }
}

// ---------------------------------------------------------------------------
// Offset/mask head: 3x3 conv 64 -> 27 channels, then
//   channels 0..17 -> offset = 15*tanh,  channels 18..26 -> mask = sigmoid.
// Same tiling, COB = 9, grid.y = 3.
// ---------------------------------------------------------------------------
__global__ __launch_bounds__(256)
void conv_offset_kernel(const float* __restrict__ in, const float* __restrict__ w,
                        const float* __restrict__ bias,
                        float* __restrict__ off_out, float* __restrict__ mask_out)
{
    constexpr int CI = 64, COB = 9;
    __shared__ float sw[COB * CI * 9];
    const int t   = threadIdx.x;
    const int cog = blockIdx.y;
    const int b   = blockIdx.z;

    const float* wsrc = w + (size_t)cog * COB * CI * 9;
    for (int i = t; i < COB * CI * 9; i += 256) sw[i] = wsrc[i];
    __syncthreads();

    const int tx = t & 31, ty = t >> 5;
    const int y  = blockIdx.x * 8 + ty;
    const int x0 = tx * 4;

    float acc[COB][4];
#pragma unroll
    for (int o = 0; o < COB; o++)
#pragma unroll
        for (int p = 0; p < 4; p++) acc[o][p] = 0.f;

    const bool vt = (y > 0), vb = (y < H - 1), vl = (x0 > 0), vr = (x0 + 4 < W);

    for (int ci = 0; ci < CI; ci++) {
        const float* p = in + ((size_t)b * CI + ci) * HW;
        float r[3][6];
        {
            const float* rp = p + y * W;
            float4 v = *(const float4*)(rp + x0);
            r[1][1] = v.x; r[1][2] = v.y; r[1][3] = v.z; r[1][4] = v.w;
            r[1][0] = vl ? rp[x0 - 1] : 0.f;
            r[1][5] = vr ? rp[x0 + 4] : 0.f;
        }
        {
            const float* rp = p + (y - 1) * W;
            float4 v = vt ? *(const float4*)(rp + x0) : make_float4(0.f, 0.f, 0.f, 0.f);
            r[0][1] = v.x; r[0][2] = v.y; r[0][3] = v.z; r[0][4] = v.w;
            r[0][0] = (vt && vl) ? rp[x0 - 1] : 0.f;
            r[0][5] = (vt && vr) ? rp[x0 + 4] : 0.f;
        }
        {
            const float* rp = p + (y + 1) * W;
            float4 v = vb ? *(const float4*)(rp + x0) : make_float4(0.f, 0.f, 0.f, 0.f);
            r[2][1] = v.x; r[2][2] = v.y; r[2][3] = v.z; r[2][4] = v.w;
            r[2][0] = (vb && vl) ? rp[x0 - 1] : 0.f;
            r[2][5] = (vb && vr) ? rp[x0 + 4] : 0.f;
        }

        const float* wci = sw + ci * 9;
#pragma unroll
        for (int tap = 0; tap < 9; tap++) {
            const int dy = tap / 3, dx = tap - dy * 3;
            float wv[COB];
#pragma unroll
            for (int o = 0; o < COB; o++) wv[o] = wci[o * (CI * 9) + tap];
#pragma unroll
            for (int px = 0; px < 4; px++) {
                const float xv = r[dy][px + dx];
#pragma unroll
                for (int o = 0; o < COB; o++) acc[o][px] = fmaf(xv, wv[o], acc[o][px]);
            }
        }
    }

#pragma unroll
    for (int o = 0; o < COB; o++) {
        const int co = cog * COB + o;
        const float bb = bias[co];
        if (co < 18) {
            float* op = off_out + ((size_t)b * 18 + co) * HW + y * W + x0;
#pragma unroll
            for (int px = 0; px < 4; px++) op[px] = 15.f * tanhf(acc[o][px] + bb);
        } else {
            float* op = mask_out + ((size_t)b * 9 + (co - 18)) * HW + y * W + x0;
#pragma unroll
            for (int px = 0; px < 4; px++) {
                const float v = acc[o][px] + bb;
                op[px] = 1.f / (1.f + expf(-v));
            }
        }
    }
}

// ---------------------------------------------------------------------------
// Modulated deformable conv (DCNv2) + leaky ReLU.
// Block: 256 threads, tile = 64 pixels of one row (b, y, x0..x0+63), all 64 co.
// Stage 0: per (px, tap) descriptors: 4 corner gather indices + mask-folded
//          bilinear weights (zeroed when out of bounds) in smem.
// Loop over 8 input-channel chunks (8 ch each):
//   A) gather+combine samples into S[72ck][64px] in smem (lane = px -> near-
//      coalesced gathers, L2-resident input), stage W chunk [64o][72ck];
//   B) smem GEMM: each thread owns 2 px x 8 o accumulators.
// Grid: (W/64, H, B). Dynamic smem = 54 KB.
// ---------------------------------------------------------------------------
__global__ __launch_bounds__(256)
void dcn_kernel(const float* __restrict__ x, const float* __restrict__ offs,
                const float* __restrict__ mask, const float* __restrict__ wd,
                const float* __restrict__ bias, float* __restrict__ out)
{
    extern __shared__ char smem_raw[];
    int*   sIdx = (int*)smem_raw;                    // [4][9][64]  9216 B
    float* sWt  = (float*)(smem_raw + 9216);         // [4][9][64]  9216 B
    float* sS   = (float*)(smem_raw + 18432);        // [72][64]   18432 B
    float* sWd  = (float*)(smem_raw + 36864);        // [64][72]   18432 B

    const int t  = threadIdx.x;
    const int x0 = blockIdx.x * 64;
    const int y  = blockIdx.y;
    const int b  = blockIdx.z;

    // Stage 0: tap descriptors
    for (int i = t; i < 64 * K; i += 256) {
        const int px = i & 63;
        const int k  = i >> 6;
        const int xx = x0 + px;
        const int base = y * W + xx;
        const float oy = offs[((size_t)b * 18 + 2 * k) * HW + base];
        const float ox = offs[((size_t)b * 18 + 2 * k + 1) * HW + base];
        const float m  = mask[((size_t)b * K + k) * HW + base];
        const float py  = (float)(y + k / 3 - 1) + oy;
        const float pxx = (float)(xx + k % 3 - 1) + ox;
        const float fy = floorf(py), fx = floorf(pxx);
        const float wy = py - fy,  wx = pxx - fx;
        const int iy0 = (int)fy, ix0 = (int)fx;
#pragma unroll
        for (int c2 = 0; c2 < 4; c2++) {
            const int yy = iy0 + (c2 >> 1);
            const int xc = ix0 + (c2 & 1);
            const bool v = (yy >= 0) && (yy < H) && (xc >= 0) && (xc < W);
            const float wgt = ((c2 >> 1) ? wy : 1.f - wy) * ((c2 & 1) ? wx : 1.f - wx) * m;
            sIdx[(c2 * K + k) * 64 + px] = v ? (yy * W + xc) : 0;
            sWt [(c2 * K + k) * 64 + px] = v ? wgt : 0.f;
        }
    }
    __syncthreads();

    const int lane = t & 31;
    const int og   = t >> 5;
    float acc0[8], acc1[8];
#pragma unroll
    for (int o = 0; o < 8; o++) { acc0[o] = 0.f; acc1[o] = 0.f; }

    for (int cc = 0; cc < 8; cc++) {
        // stage weight chunk: wd[o][cc*8 .. cc*8+7][k] -> sWd[o][0..71]
        for (int i = t; i < 64 * 72; i += 256) {
            const int o = i / 72, l = i - o * 72;
            sWd[o * 72 + l] = wd[(size_t)o * 576 + cc * 72 + l];
        }
        // compute S chunk
        const float* xb = x + ((size_t)b * NF + cc * 8) * HW;
        for (int i = t; i < 72 * 64; i += 256) {
            const int px = i & 63;
            const int l  = i >> 6;           // 0..71 : (c_local, k)
            const int c  = l / 9, k = l - c * 9;
            const float* xp = xb + (size_t)c * HW;
            float s = 0.f;
#pragma unroll
            for (int c2 = 0; c2 < 4; c2++)
                s = fmaf(sWt[(c2 * K + k) * 64 + px],
                         __ldg(xp + sIdx[(c2 * K + k) * 64 + px]), s);
            sS[l * 64 + px] = s;
        }
        __syncthreads();

#pragma unroll 4
        for (int l = 0; l < 72; l++) {
            const float s0 = sS[l * 64 + lane];
            const float s1 = sS[l * 64 + lane + 32];
#pragma unroll
            for (int o = 0; o < 8; o++) {
                const float wv = sWd[(og * 8 + o) * 72 + l];
                acc0[o] = fmaf(s0, wv, acc0[o]);
                acc1[o] = fmaf(s1, wv, acc1[o]);
            }
        }
        __syncthreads();
    }

#pragma unroll
    for (int o = 0; o < 8; o++) {
        const int co = og * 8 + o;
        const float bb = bias[co];
        float* op = out + ((size_t)b * NF + co) * HW + y * W + x0;
        op[lane]      = lrelu(acc0[o] + bb);
        op[lane + 32] = lrelu(acc1[o] + bb);
    }
}

// ---------------------------------------------------------------------------
extern "C" void kernel_launch(void* const* d_in, const int* in_sizes, int n_in,
                              void* d_out, int out_size)
{
    const float* nbr   = (const float*)d_in[0];
    const float* ref   = (const float*)d_in[1];
    const float* w1    = (const float*)d_in[2];
    const float* b1    = (const float*)d_in[3];
    const float* w2    = (const float*)d_in[4];
    const float* b2    = (const float*)d_in[5];
    const float* w3    = (const float*)d_in[6];
    const float* b3    = (const float*)d_in[7];
    const float* w_off = (const float*)d_in[8];
    const float* b_off = (const float*)d_in[9];
    const float* w_dcn = (const float*)d_in[10];
    const float* b_dcn = (const float*)d_in[11];

    float* out  = (float*)d_out;
    float* feat = out;                                   // [B,64,H,W]
    float* offs = out + (size_t)BN * NF * HW;            // [B,18,H,W]
    float* msk  = offs + (size_t)BN * 18 * HW;           // [B, 9,H,W]

    float *bufA, *bufB;
    cudaGetSymbolAddress((void**)&bufA, g_bufA);
    cudaGetSymbolAddress((void**)&bufB, g_bufB);

    conv3x3_lrelu_kernel<128, 64, 8, true ><<<dim3(16, 8, 4), 256>>>(nbr, ref, w1, b1, bufA);
    conv3x3_lrelu_kernel< 64, 64, 8, false><<<dim3(16, 8, 4), 256>>>(bufA, bufA, w2, b2, bufB);
    conv3x3_lrelu_kernel< 64, 64, 8, false><<<dim3(16, 8, 4), 256>>>(bufB, bufB, w3, b3, bufA);
    conv_offset_kernel<<<dim3(16, 3, 4), 256>>>(bufA, w_off, b_off, offs, msk);

    const int dcn_smem = 9216 + 9216 + 18432 + 18432;    // 55296 B
    cudaFuncSetAttribute(dcn_kernel, cudaFuncAttributeMaxDynamicSharedMemorySize, dcn_smem);
    dcn_kernel<<<dim3(2, 128, 4), 256, dcn_smem>>>(nbr, offs, msk, w_dcn, b_dcn, feat);
}

// round 2
// speedup vs baseline: 1.0341x; 1.0341x over previous
#include <cuda_runtime.h>
#include <math.h>

// Problem constants
constexpr int BN = 4;
constexpr int NF = 64;
constexpr int H  = 128;
constexpr int W  = 128;
constexpr int HW = H * W;
constexpr int K  = 9;

// Scratch (device globals: no runtime allocation allowed)
__device__ float g_bufA[BN * NF * HW];
__device__ float g_bufB[BN * NF * HW];

__device__ __forceinline__ float lrelu(float v) { return v >= 0.f ? v : 0.1f * v; }

// ---- packed f32x2 helpers (sm_103a FFMA2 path) ------------------------------
using u64 = unsigned long long;

__device__ __forceinline__ u64 pack2(float lo, float hi) {
    u64 r;
    asm("mov.b64 %0, {%1, %2};" : "=l"(r) : "f"(lo), "f"(hi));
    return r;
}
__device__ __forceinline__ u64 dup2(float v) { return pack2(v, v); }

__device__ __forceinline__ void ffma2(u64& acc, u64 a, u64 b) {
    asm("fma.rn.f32x2 %0, %1, %2, %0;" : "+l"(acc) : "l"(a), "l"(b));
}
__device__ __forceinline__ float2 unpack2(u64 v) {
    float2 f;
    asm("mov.b64 {%0, %1}, %2;" : "=f"(f.x), "=f"(f.y) : "l"(v));
    return f;
}

// ---------------------------------------------------------------------------
// 3x3 conv + leaky ReLU, packed output-channel pairs (COB = 8 -> 4 f32x2 pairs).
// Block: 256 threads = 32 x-groups (4 px each) x 8 rows.
// Weights staged in smem as [ci][tap][o] (o innermost) -> warp-uniform LDS.64
// fetches an o-pair. Each thread: 4 px x 4 pairs of f32x2 accumulators.
// Grid: (H/8, CO/8, B)
// ---------------------------------------------------------------------------
template <int CI, int CO, bool CONCAT>
__global__ __launch_bounds__(256)
void conv3x3p_kernel(const float* __restrict__ inA, const float* __restrict__ inB,
                     const float* __restrict__ w, const float* __restrict__ bias,
                     float* __restrict__ out)
{
    __shared__ float sw[CI * 9 * 8];              // [ci][tap][o]
    const int t   = threadIdx.x;
    const int cog = blockIdx.y;
    const int b   = blockIdx.z;

    // stage + transpose weights: read coalesced, write [rest][o]
    const float* wsrc = w + (size_t)cog * 8 * CI * 9;
    for (int i = t; i < 8 * CI * 9; i += 256) {
        const int o = i / (CI * 9);
        const int rest = i - o * (CI * 9);        // rest = ci*9 + tap
        sw[rest * 8 + o] = wsrc[o * (CI * 9) + rest];
    }
    __syncthreads();

    const int tx = t & 31, ty = t >> 5;
    const int y  = blockIdx.x * 8 + ty;
    const int x0 = tx * 4;

    u64 acc[4][4];                                // [pair][px]
#pragma unroll
    for (int pr = 0; pr < 4; pr++)
#pragma unroll
        for (int p = 0; p < 4; p++) acc[pr][p] = 0ULL;

    const bool vt = (y > 0), vb = (y < H - 1), vl = (x0 > 0), vr = (x0 + 4 < W);

    for (int ci = 0; ci < CI; ci++) {
        const float* p;
        if (CONCAT)
            p = (ci < NF) ? (inA + ((size_t)b * NF + ci) * HW)
                          : (inB + ((size_t)b * NF + (ci - NF)) * HW);
        else
            p = inA + ((size_t)b * CI + ci) * HW;

        float r[3][6];
        {   // row y (always valid)
            const float* rp = p + y * W;
            float4 v = *(const float4*)(rp + x0);
            r[1][1] = v.x; r[1][2] = v.y; r[1][3] = v.z; r[1][4] = v.w;
            r[1][0] = vl ? rp[x0 - 1] : 0.f;
            r[1][5] = vr ? rp[x0 + 4] : 0.f;
        }
        {   // row y-1
            const float* rp = p + (y - 1) * W;
            float4 v = vt ? *(const float4*)(rp + x0) : make_float4(0.f, 0.f, 0.f, 0.f);
            r[0][1] = v.x; r[0][2] = v.y; r[0][3] = v.z; r[0][4] = v.w;
            r[0][0] = (vt && vl) ? rp[x0 - 1] : 0.f;
            r[0][5] = (vt && vr) ? rp[x0 + 4] : 0.f;
        }
        {   // row y+1
            const float* rp = p + (y + 1) * W;
            float4 v = vb ? *(const float4*)(rp + x0) : make_float4(0.f, 0.f, 0.f, 0.f);
            r[2][1] = v.x; r[2][2] = v.y; r[2][3] = v.z; r[2][4] = v.w;
            r[2][0] = (vb && vl) ? rp[x0 - 1] : 0.f;
            r[2][5] = (vb && vr) ? rp[x0 + 4] : 0.f;
        }

        const float* wci = sw + ci * 72;
#pragma unroll
        for (int dy = 0; dy < 3; dy++) {
            u64 xp[6];
#pragma unroll
            for (int j = 0; j < 6; j++) xp[j] = dup2(r[dy][j]);
#pragma unroll
            for (int dx = 0; dx < 3; dx++) {
                const int tap = dy * 3 + dx;
                const u64* wp = (const u64*)(wci + tap * 8);
                u64 wv[4];
#pragma unroll
                for (int pr = 0; pr < 4; pr++) wv[pr] = wp[pr];   // uniform LDS.64
#pragma unroll
                for (int px = 0; px < 4; px++)
#pragma unroll
                    for (int pr = 0; pr < 4; pr++)
                        ffma2(acc[pr][px], xp[px + dx], wv[pr]);
            }
        }
    }

#pragma unroll
    for (int pr = 0; pr < 4; pr++) {
        const int co0 = cog * 8 + 2 * pr;
        const float b0 = bias[co0], b1 = bias[co0 + 1];
        float4 v0, v1;
        float2 u;
        u = unpack2(acc[pr][0]); v0.x = lrelu(u.x + b0); v1.x = lrelu(u.y + b1);
        u = unpack2(acc[pr][1]); v0.y = lrelu(u.x + b0); v1.y = lrelu(u.y + b1);
        u = unpack2(acc[pr][2]); v0.z = lrelu(u.x + b0); v1.z = lrelu(u.y + b1);
        u = unpack2(acc[pr][3]); v0.w = lrelu(u.x + b0); v1.w = lrelu(u.y + b1);
        *(float4*)(out + ((size_t)b * CO + co0)     * HW + y * W + x0) = v0;
        *(float4*)(out + ((size_t)b * CO + co0 + 1) * HW + y * W + x0) = v1;
    }
}

// ---------------------------------------------------------------------------
// Offset/mask head: 3x3 conv 64 -> 27, CO slice of 9 = 4 o-pairs + 1 scalar.
// cog 0,1 -> offset channels (15*tanh), cog 2 -> mask channels (sigmoid).
// Weights staged as [ci][tap][o(pad 10)] so pair LDS.64 stays 8B-aligned.
// Grid: (16, 3, B)
// ---------------------------------------------------------------------------
__global__ __launch_bounds__(256)
void conv_offset_kernel(const float* __restrict__ in, const float* __restrict__ w,
                        const float* __restrict__ bias,
                        float* __restrict__ off_out, float* __restrict__ mask_out)
{
    constexpr int CI = 64;
    __shared__ float sw[CI * 9 * 10];
    const int t   = threadIdx.x;
    const int cog = blockIdx.y;
    const int b   = blockIdx.z;

    const float* wsrc = w + (size_t)cog * 9 * CI * 9;
    for (int i = t; i < 9 * CI * 9; i += 256) {
        const int o = i / (CI * 9);
        const int rest = i - o * (CI * 9);
        sw[rest * 10 + o] = wsrc[o * (CI * 9) + rest];
    }
    __syncthreads();

    const int tx = t & 31, ty = t >> 5;
    const int y  = blockIdx.x * 8 + ty;
    const int x0 = tx * 4;

    u64 accp[4][4];
    float accs[4];
#pragma unroll
    for (int pr = 0; pr < 4; pr++)
#pragma unroll
        for (int p = 0; p < 4; p++) accp[pr][p] = 0ULL;
#pragma unroll
    for (int p = 0; p < 4; p++) accs[p] = 0.f;

    const bool vt = (y > 0), vb = (y < H - 1), vl = (x0 > 0), vr = (x0 + 4 < W);

    for (int ci = 0; ci < CI; ci++) {
        const float* p = in + ((size_t)b * CI + ci) * HW;
        float r[3][6];
        {
            const float* rp = p + y * W;
            float4 v = *(const float4*)(rp + x0);
            r[1][1] = v.x; r[1][2] = v.y; r[1][3] = v.z; r[1][4] = v.w;
            r[1][0] = vl ? rp[x0 - 1] : 0.f;
            r[1][5] = vr ? rp[x0 + 4] : 0.f;
        }
        {
            const float* rp = p + (y - 1) * W;
            float4 v = vt ? *(const float4*)(rp + x0) : make_float4(0.f, 0.f, 0.f, 0.f);
            r[0][1] = v.x; r[0][2] = v.y; r[0][3] = v.z; r[0][4] = v.w;
            r[0][0] = (vt && vl) ? rp[x0 - 1] : 0.f;
            r[0][5] = (vt && vr) ? rp[x0 + 4] : 0.f;
        }
        {
            const float* rp = p + (y + 1) * W;
            float4 v = vb ? *(const float4*)(rp + x0) : make_float4(0.f, 0.f, 0.f, 0.f);
            r[2][1] = v.x; r[2][2] = v.y; r[2][3] = v.z; r[2][4] = v.w;
            r[2][0] = (vb && vl) ? rp[x0 - 1] : 0.f;
            r[2][5] = (vb && vr) ? rp[x0 + 4] : 0.f;
        }

        const float* wci = sw + ci * 90;
#pragma unroll
        for (int dy = 0; dy < 3; dy++) {
            u64 xp[6];
#pragma unroll
            for (int j = 0; j < 6; j++) xp[j] = dup2(r[dy][j]);
#pragma unroll
            for (int dx = 0; dx < 3; dx++) {
                const int tap = dy * 3 + dx;
                const u64* wp = (const u64*)(wci + tap * 10);
                u64 wv[4];
#pragma unroll
                for (int pr = 0; pr < 4; pr++) wv[pr] = wp[pr];
                const float ws = wci[tap * 10 + 8];
#pragma unroll
                for (int px = 0; px < 4; px++) {
#pragma unroll
                    for (int pr = 0; pr < 4; pr++)
                        ffma2(accp[pr][px], xp[px + dx], wv[pr]);
                    accs[px] = fmaf(r[dy][px + dx], ws, accs[px]);
                }
            }
        }
    }

    const bool is_off = (cog < 2);
    float vals[9][4];
#pragma unroll
    for (int pr = 0; pr < 4; pr++) {
        const int co = cog * 9 + 2 * pr;
        const float b0 = bias[co], b1 = bias[co + 1];
#pragma unroll
        for (int px = 0; px < 4; px++) {
            float2 u = unpack2(accp[pr][px]);
            vals[2 * pr][px]     = u.x + b0;
            vals[2 * pr + 1][px] = u.y + b1;
        }
    }
    {
        const float bb = bias[cog * 9 + 8];
#pragma unroll
        for (int px = 0; px < 4; px++) vals[8][px] = accs[px] + bb;
    }

#pragma unroll
    for (int o = 0; o < 9; o++) {
        const int co = cog * 9 + o;
        float4 v;
        if (is_off) {
            v.x = 15.f * tanhf(vals[o][0]);
            v.y = 15.f * tanhf(vals[o][1]);
            v.z = 15.f * tanhf(vals[o][2]);
            v.w = 15.f * tanhf(vals[o][3]);
            *(float4*)(off_out + ((size_t)b * 18 + co) * HW + y * W + x0) = v;
        } else {
            v.x = 1.f / (1.f + expf(-vals[o][0]));
            v.y = 1.f / (1.f + expf(-vals[o][1]));
            v.z = 1.f / (1.f + expf(-vals[o][2]));
            v.w = 1.f / (1.f + expf(-vals[o][3]));
            *(float4*)(mask_out + ((size_t)b * 9 + (co - 18)) * HW + y * W + x0) = v;
        }
    }
}

// ---------------------------------------------------------------------------
// Modulated deformable conv (DCNv2) + leaky ReLU, packed pixel pairs.
// Block: 256 threads, tile = 64 pixels of one row, all 64 co.
// GEMM: lane owns pixel pair (2*lane, 2*lane+1) -> one LDS.64 from S tile;
// weights staged pre-duplicated {w,w} -> one LDS.64 per o. 8 FFMA2 / l / thread.
// Grid: (W/64, H, B). Dynamic smem = 72 KB.
// ---------------------------------------------------------------------------
__global__ __launch_bounds__(256)
void dcn_kernel(const float* __restrict__ x, const float* __restrict__ offs,
                const float* __restrict__ mask, const float* __restrict__ wd,
                const float* __restrict__ bias, float* __restrict__ out)
{
    extern __shared__ char smem_raw[];
    int*   sIdx = (int*)smem_raw;                    // [4][9][64]   9216 B
    float* sWt  = (float*)(smem_raw + 9216);         // [4][9][64]   9216 B
    float* sS   = (float*)(smem_raw + 18432);        // [72][64]    18432 B
    u64*   sWdD = (u64*)(smem_raw + 36864);          // [64][72] dup 36864 B

    const int t  = threadIdx.x;
    const int x0 = blockIdx.x * 64;
    const int y  = blockIdx.y;
    const int b  = blockIdx.z;

    // Stage 0: tap descriptors
    for (int i = t; i < 64 * K; i += 256) {
        const int px = i & 63;
        const int k  = i >> 6;
        const int xx = x0 + px;
        const int base = y * W + xx;
        const float oy = offs[((size_t)b * 18 + 2 * k) * HW + base];
        const float ox = offs[((size_t)b * 18 + 2 * k + 1) * HW + base];
        const float m  = mask[((size_t)b * K + k) * HW + base];
        const float py  = (float)(y + k / 3 - 1) + oy;
        const float pxx = (float)(xx + k % 3 - 1) + ox;
        const float fy = floorf(py), fx = floorf(pxx);
        const float wy = py - fy,  wx = pxx - fx;
        const int iy0 = (int)fy, ix0 = (int)fx;
#pragma unroll
        for (int c2 = 0; c2 < 4; c2++) {
            const int yy = iy0 + (c2 >> 1);
            const int xc = ix0 + (c2 & 1);
            const bool v = (yy >= 0) && (yy < H) && (xc >= 0) && (xc < W);
            const float wgt = ((c2 >> 1) ? wy : 1.f - wy) * ((c2 & 1) ? wx : 1.f - wx) * m;
            sIdx[(c2 * K + k) * 64 + px] = v ? (yy * W + xc) : 0;
            sWt [(c2 * K + k) * 64 + px] = v ? wgt : 0.f;
        }
    }
    __syncthreads();

    const int lane = t & 31;
    const int og   = t >> 5;
    u64 acc[8];
#pragma unroll
    for (int o = 0; o < 8; o++) acc[o] = 0ULL;

    for (int cc = 0; cc < 8; cc++) {
        // stage weight chunk, duplicated: sWdD[o*72 + l] = {w, w}
        for (int i = t; i < 64 * 72; i += 256) {
            const int o = i / 72, l = i - o * 72;
            sWdD[o * 72 + l] = dup2(wd[(size_t)o * 576 + cc * 72 + l]);
        }
        // compute S chunk (gather + bilinear/mask combine)
        const float* xb = x + ((size_t)b * NF + cc * 8) * HW;
        for (int i = t; i < 72 * 64; i += 256) {
            const int px = i & 63;
            const int l  = i >> 6;           // 0..71 : (c_local, k)
            const int c  = l / 9, k = l - c * 9;
            const float* xp = xb + (size_t)c * HW;
            float s = 0.f;
#pragma unroll
            for (int c2 = 0; c2 < 4; c2++)
                s = fmaf(sWt[(c2 * K + k) * 64 + px],
                         __ldg(xp + sIdx[(c2 * K + k) * 64 + px]), s);
            sS[l * 64 + px] = s;
        }
        __syncthreads();

        const u64* sS64 = (const u64*)sS;
        const u64* wbase = sWdD + og * 8 * 72;
#pragma unroll 4
        for (int l = 0; l < 72; l++) {
            const u64 s = sS64[l * 32 + lane];          // pixel pair
#pragma unroll
            for (int o = 0; o < 8; o++)
                ffma2(acc[o], s, wbase[o * 72 + l]);    // uniform LDS.64
        }
        __syncthreads();
    }

#pragma unroll
    for (int o = 0; o < 8; o++) {
        const int co = og * 8 + o;
        const float bb = bias[co];
        float2 u = unpack2(acc[o]);
        float2 v;
        v.x = lrelu(u.x + bb);
        v.y = lrelu(u.y + bb);
        *(float2*)(out + ((size_t)b * NF + co) * HW + y * W + x0 + 2 * lane) = v;
    }
}

// ---------------------------------------------------------------------------
extern "C" void kernel_launch(void* const* d_in, const int* in_sizes, int n_in,
                              void* d_out, int out_size)
{
    const float* nbr   = (const float*)d_in[0];
    const float* ref   = (const float*)d_in[1];
    const float* w1    = (const float*)d_in[2];
    const float* b1    = (const float*)d_in[3];
    const float* w2    = (const float*)d_in[4];
    const float* b2    = (const float*)d_in[5];
    const float* w3    = (const float*)d_in[6];
    const float* b3    = (const float*)d_in[7];
    const float* w_off = (const float*)d_in[8];
    const float* b_off = (const float*)d_in[9];
    const float* w_dcn = (const float*)d_in[10];
    const float* b_dcn = (const float*)d_in[11];

    float* out  = (float*)d_out;
    float* feat = out;                                   // [B,64,H,W]
    float* offs = out + (size_t)BN * NF * HW;            // [B,18,H,W]
    float* msk  = offs + (size_t)BN * 18 * HW;           // [B, 9,H,W]

    float *bufA, *bufB;
    cudaGetSymbolAddress((void**)&bufA, g_bufA);
    cudaGetSymbolAddress((void**)&bufB, g_bufB);

    conv3x3p_kernel<128, 64, true ><<<dim3(16, 8, 4), 256>>>(nbr, ref, w1, b1, bufA);
    conv3x3p_kernel< 64, 64, false><<<dim3(16, 8, 4), 256>>>(bufA, bufA, w2, b2, bufB);
    conv3x3p_kernel< 64, 64, false><<<dim3(16, 8, 4), 256>>>(bufB, bufB, w3, b3, bufA);
    conv_offset_kernel<<<dim3(16, 3, 4), 256>>>(bufA, w_off, b_off, offs, msk);

    const int dcn_smem = 9216 + 9216 + 18432 + 36864;    // 73728 B
    cudaFuncSetAttribute(dcn_kernel, cudaFuncAttributeMaxDynamicSharedMemorySize, dcn_smem);
    dcn_kernel<<<dim3(2, 128, 4), 256, dcn_smem>>>(nbr, offs, msk, w_dcn, b_dcn, feat);
}

// round 3
// speedup vs baseline: 1.2006x; 1.1610x over previous
#include <cuda_runtime.h>
#include <math.h>

// Problem constants
constexpr int BN = 4;
constexpr int NF = 64;
constexpr int H  = 128;
constexpr int W  = 128;
constexpr int HW = H * W;
constexpr int K  = 9;

// Scratch (device globals: no runtime allocation allowed)
__device__ float g_bufA[BN * NF * HW];
__device__ float g_bufB[BN * NF * HW];
__device__ float g_wT[NF * NF * 9];          // DCN weights transposed [cc][l][o]

__device__ __forceinline__ float lrelu(float v) { return v >= 0.f ? v : 0.1f * v; }

// ---- packed f32x2 helpers (sm_103a FFMA2 path) ------------------------------
using u64 = unsigned long long;

__device__ __forceinline__ u64 pack2(float lo, float hi) {
    u64 r;
    asm("mov.b64 %0, {%1, %2};" : "=l"(r) : "f"(lo), "f"(hi));
    return r;
}
__device__ __forceinline__ u64 dup2(float v) { return pack2(v, v); }

__device__ __forceinline__ void ffma2(u64& acc, u64 a, u64 b) {
    asm("fma.rn.f32x2 %0, %1, %2, %0;" : "+l"(acc) : "l"(a), "l"(b));
}
__device__ __forceinline__ float2 unpack2(u64 v) {
    float2 f;
    asm("mov.b64 {%0, %1}, %2;" : "=f"(f.x), "=f"(f.y) : "l"(v));
    return f;
}

// ---------------------------------------------------------------------------
// 3x3 conv + leaky ReLU, packed output-channel pairs.
// Block: 128 threads = 32 x-groups (4 px) x 4 rows. Grid: (32, CO/8, B).
// Weights in smem as [ci][tap][o]; o-pair fetched by warp-uniform LDS.64.
// ---------------------------------------------------------------------------
template <int CI, int CO, bool CONCAT>
__global__ __launch_bounds__(128, 6)
void conv3x3p_kernel(const float* __restrict__ inA, const float* __restrict__ inB,
                     const float* __restrict__ w, const float* __restrict__ bias,
                     float* __restrict__ out)
{
    __shared__ float sw[CI * 9 * 8];              // [ci][tap][o]
    const int t   = threadIdx.x;
    const int cog = blockIdx.y;
    const int b   = blockIdx.z;

    const float* wsrc = w + (size_t)cog * 8 * CI * 9;
    for (int i = t; i < 8 * CI * 9; i += 128) {
        const int o = i / (CI * 9);
        const int rest = i - o * (CI * 9);        // rest = ci*9 + tap
        sw[rest * 8 + o] = wsrc[o * (CI * 9) + rest];
    }
    __syncthreads();

    const int tx = t & 31, ty = t >> 5;
    const int y  = blockIdx.x * 4 + ty;
    const int x0 = tx * 4;

    u64 acc[4][4];                                // [pair][px]
#pragma unroll
    for (int pr = 0; pr < 4; pr++)
#pragma unroll
        for (int p = 0; p < 4; p++) acc[pr][p] = 0ULL;

    const bool vt = (y > 0), vb = (y < H - 1), vl = (x0 > 0), vr = (x0 + 4 < W);

    for (int ci = 0; ci < CI; ci++) {
        const float* p;
        if (CONCAT)
            p = (ci < NF) ? (inA + ((size_t)b * NF + ci) * HW)
                          : (inB + ((size_t)b * NF + (ci - NF)) * HW);
        else
            p = inA + ((size_t)b * CI + ci) * HW;

        float r[3][6];
        {
            const float* rp = p + y * W;
            float4 v = *(const float4*)(rp + x0);
            r[1][1] = v.x; r[1][2] = v.y; r[1][3] = v.z; r[1][4] = v.w;
            r[1][0] = vl ? rp[x0 - 1] : 0.f;
            r[1][5] = vr ? rp[x0 + 4] : 0.f;
        }
        {
            const float* rp = p + (y - 1) * W;
            float4 v = vt ? *(const float4*)(rp + x0) : make_float4(0.f, 0.f, 0.f, 0.f);
            r[0][1] = v.x; r[0][2] = v.y; r[0][3] = v.z; r[0][4] = v.w;
            r[0][0] = (vt && vl) ? rp[x0 - 1] : 0.f;
            r[0][5] = (vt && vr) ? rp[x0 + 4] : 0.f;
        }
        {
            const float* rp = p + (y + 1) * W;
            float4 v = vb ? *(const float4*)(rp + x0) : make_float4(0.f, 0.f, 0.f, 0.f);
            r[2][1] = v.x; r[2][2] = v.y; r[2][3] = v.z; r[2][4] = v.w;
            r[2][0] = (vb && vl) ? rp[x0 - 1] : 0.f;
            r[2][5] = (vb && vr) ? rp[x0 + 4] : 0.f;
        }

        const float* wci = sw + ci * 72;
#pragma unroll
        for (int dy = 0; dy < 3; dy++) {
            u64 xp[6];
#pragma unroll
            for (int j = 0; j < 6; j++) xp[j] = dup2(r[dy][j]);
#pragma unroll
            for (int dx = 0; dx < 3; dx++) {
                const int tap = dy * 3 + dx;
                const u64* wp = (const u64*)(wci + tap * 8);
                u64 wv[4];
#pragma unroll
                for (int pr = 0; pr < 4; pr++) wv[pr] = wp[pr];   // uniform LDS.64
#pragma unroll
                for (int px = 0; px < 4; px++)
#pragma unroll
                    for (int pr = 0; pr < 4; pr++)
                        ffma2(acc[pr][px], xp[px + dx], wv[pr]);
            }
        }
    }

#pragma unroll
    for (int pr = 0; pr < 4; pr++) {
        const int co0 = cog * 8 + 2 * pr;
        const float b0 = bias[co0], b1 = bias[co0 + 1];
        float4 v0, v1;
        float2 u;
        u = unpack2(acc[pr][0]); v0.x = lrelu(u.x + b0); v1.x = lrelu(u.y + b1);
        u = unpack2(acc[pr][1]); v0.y = lrelu(u.x + b0); v1.y = lrelu(u.y + b1);
        u = unpack2(acc[pr][2]); v0.z = lrelu(u.x + b0); v1.z = lrelu(u.y + b1);
        u = unpack2(acc[pr][3]); v0.w = lrelu(u.x + b0); v1.w = lrelu(u.y + b1);
        *(float4*)(out + ((size_t)b * CO + co0)     * HW + y * W + x0) = v0;
        *(float4*)(out + ((size_t)b * CO + co0 + 1) * HW + y * W + x0) = v1;
    }
}

// ---------------------------------------------------------------------------
// Offset/mask head: 3x3 conv 64 -> 27 (slice of 9 = 4 o-pairs + 1 scalar).
// Block: 128 threads = 64 x-groups (2 px) x 2 rows. Grid: (64, 3, B).
// cog 0,1 -> offset (15*tanh), cog 2 -> mask (sigmoid).
// ---------------------------------------------------------------------------
__global__ __launch_bounds__(128, 8)
void conv_offset_kernel(const float* __restrict__ in, const float* __restrict__ w,
                        const float* __restrict__ bias,
                        float* __restrict__ off_out, float* __restrict__ mask_out)
{
    constexpr int CI = 64;
    __shared__ float sw[CI * 9 * 10];             // [ci][tap][o pad10]
    const int t   = threadIdx.x;
    const int cog = blockIdx.y;
    const int b   = blockIdx.z;

    const float* wsrc = w + (size_t)cog * 9 * CI * 9;
    for (int i = t; i < 9 * CI * 9; i += 128) {
        const int o = i / (CI * 9);
        const int rest = i - o * (CI * 9);
        sw[rest * 10 + o] = wsrc[o * (CI * 9) + rest];
    }
    __syncthreads();

    const int tx = t & 63, ty = t >> 6;
    const int y  = blockIdx.x * 2 + ty;
    const int x0 = tx * 2;

    u64 accp[4][2];
    float accs[2];
#pragma unroll
    for (int pr = 0; pr < 4; pr++) { accp[pr][0] = 0ULL; accp[pr][1] = 0ULL; }
    accs[0] = accs[1] = 0.f;

    const bool vt = (y > 0), vb = (y < H - 1), vl = (x0 > 0), vr = (x0 + 2 < W);

    for (int ci = 0; ci < CI; ci++) {
        const float* p = in + ((size_t)b * CI + ci) * HW;
        float r[3][4];
        {
            const float* rp = p + y * W;
            float2 v = *(const float2*)(rp + x0);
            r[1][1] = v.x; r[1][2] = v.y;
            r[1][0] = vl ? rp[x0 - 1] : 0.f;
            r[1][3] = vr ? rp[x0 + 2] : 0.f;
        }
        {
            const float* rp = p + (y - 1) * W;
            float2 v = vt ? *(const float2*)(rp + x0) : make_float2(0.f, 0.f);
            r[0][1] = v.x; r[0][2] = v.y;
            r[0][0] = (vt && vl) ? rp[x0 - 1] : 0.f;
            r[0][3] = (vt && vr) ? rp[x0 + 2] : 0.f;
        }
        {
            const float* rp = p + (y + 1) * W;
            float2 v = vb ? *(const float2*)(rp + x0) : make_float2(0.f, 0.f);
            r[2][1] = v.x; r[2][2] = v.y;
            r[2][0] = (vb && vl) ? rp[x0 - 1] : 0.f;
            r[2][3] = (vb && vr) ? rp[x0 + 2] : 0.f;
        }

        const float* wci = sw + ci * 90;
#pragma unroll
        for (int dy = 0; dy < 3; dy++) {
            u64 xp[4];
#pragma unroll
            for (int j = 0; j < 4; j++) xp[j] = dup2(r[dy][j]);
#pragma unroll
            for (int dx = 0; dx < 3; dx++) {
                const int tap = dy * 3 + dx;
                const u64* wp = (const u64*)(wci + tap * 10);
                u64 wv[4];
#pragma unroll
                for (int pr = 0; pr < 4; pr++) wv[pr] = wp[pr];
                const float ws = wci[tap * 10 + 8];
#pragma unroll
                for (int px = 0; px < 2; px++) {
#pragma unroll
                    for (int pr = 0; pr < 4; pr++)
                        ffma2(accp[pr][px], xp[px + dx], wv[pr]);
                    accs[px] = fmaf(r[dy][px + dx], ws, accs[px]);
                }
            }
        }
    }

    const bool is_off = (cog < 2);
    float vals[9][2];
#pragma unroll
    for (int pr = 0; pr < 4; pr++) {
        const int co = cog * 9 + 2 * pr;
        const float b0 = bias[co], b1 = bias[co + 1];
#pragma unroll
        for (int px = 0; px < 2; px++) {
            float2 u = unpack2(accp[pr][px]);
            vals[2 * pr][px]     = u.x + b0;
            vals[2 * pr + 1][px] = u.y + b1;
        }
    }
    {
        const float bb = bias[cog * 9 + 8];
        vals[8][0] = accs[0] + bb;
        vals[8][1] = accs[1] + bb;
    }

#pragma unroll
    for (int o = 0; o < 9; o++) {
        const int co = cog * 9 + o;
        float2 v;
        if (is_off) {
            v.x = 15.f * tanhf(vals[o][0]);
            v.y = 15.f * tanhf(vals[o][1]);
            *(float2*)(off_out + ((size_t)b * 18 + co) * HW + y * W + x0) = v;
        } else {
            v.x = 1.f / (1.f + expf(-vals[o][0]));
            v.y = 1.f / (1.f + expf(-vals[o][1]));
            *(float2*)(mask_out + ((size_t)b * 9 + (co - 18)) * HW + y * W + x0) = v;
        }
    }
}

// ---------------------------------------------------------------------------
// One-shot DCN weight transpose: wT[cc][l][o] = wd[o][cc*8 + l/9][l%9]
//   (l = c_local*9 + k, o = output channel, cc = channel chunk)
// ---------------------------------------------------------------------------
__global__ void transpose_wdcn_kernel(const float* __restrict__ wd, float* __restrict__ wT)
{
    const int i = blockIdx.x * 256 + threadIdx.x;
    if (i < NF * NF * 9) {
        const int cc = i / 4608;
        const int r  = i - cc * 4608;
        const int l  = r >> 6;
        const int o  = r & 63;
        wT[i] = wd[(size_t)o * 576 + cc * 72 + l];
    }
}

// ---------------------------------------------------------------------------
// Modulated deformable conv (DCNv2) + leaky ReLU.
// Block: 256 threads, tile = 64 px of one row, all 64 co. Grid: (2, 128, 4).
// GEMM: o-pairs (weights [l][o], uniform LDS.64) x per-pixel duplicated S.
// smem 54 KB -> 4 CTAs/SM.
// ---------------------------------------------------------------------------
__global__ __launch_bounds__(256, 4)
void dcn_kernel(const float* __restrict__ x, const float* __restrict__ offs,
                const float* __restrict__ mask, const float* __restrict__ wT,
                const float* __restrict__ bias, float* __restrict__ out)
{
    extern __shared__ char smem_raw[];
    int*   sIdx = (int*)smem_raw;                    // [4][9][64]   9216 B
    float* sWt  = (float*)(smem_raw + 9216);         // [4][9][64]   9216 B
    float* sS   = (float*)(smem_raw + 18432);        // [72][64]    18432 B
    float* sWd  = (float*)(smem_raw + 36864);        // [72][64]    18432 B

    const int t  = threadIdx.x;
    const int x0 = blockIdx.x * 64;
    const int y  = blockIdx.y;
    const int b  = blockIdx.z;

    // Stage 0: tap descriptors
    for (int i = t; i < 64 * K; i += 256) {
        const int px = i & 63;
        const int k  = i >> 6;
        const int xx = x0 + px;
        const int base = y * W + xx;
        const float oy = offs[((size_t)b * 18 + 2 * k) * HW + base];
        const float ox = offs[((size_t)b * 18 + 2 * k + 1) * HW + base];
        const float m  = mask[((size_t)b * K + k) * HW + base];
        const float py  = (float)(y + k / 3 - 1) + oy;
        const float pxx = (float)(xx + k % 3 - 1) + ox;
        const float fy = floorf(py), fx = floorf(pxx);
        const float wy = py - fy,  wx = pxx - fx;
        const int iy0 = (int)fy, ix0 = (int)fx;
#pragma unroll
        for (int c2 = 0; c2 < 4; c2++) {
            const int yy = iy0 + (c2 >> 1);
            const int xc = ix0 + (c2 & 1);
            const bool v = (yy >= 0) && (yy < H) && (xc >= 0) && (xc < W);
            const float wgt = ((c2 >> 1) ? wy : 1.f - wy) * ((c2 & 1) ? wx : 1.f - wx) * m;
            sIdx[(c2 * K + k) * 64 + px] = v ? (yy * W + xc) : 0;
            sWt [(c2 * K + k) * 64 + px] = v ? wgt : 0.f;
        }
    }
    __syncthreads();

    const int lane = t & 31;
    const int og   = t >> 5;
    u64 accA[4], accB[4];                            // px0 x 4 o-pairs, px1 x 4 o-pairs
#pragma unroll
    for (int pr = 0; pr < 4; pr++) { accA[pr] = 0ULL; accB[pr] = 0ULL; }

    for (int cc = 0; cc < 8; cc++) {
        // stage weight chunk [l][o]: coalesced read + conflict-free write
        const float* wsrc = wT + cc * 4608;
        for (int i = t; i < 4608; i += 256) sWd[i] = wsrc[i];

        // compute S chunk (gather + bilinear/mask combine)
        const float* xb = x + ((size_t)b * NF + cc * 8) * HW;
        for (int i = t; i < 72 * 64; i += 256) {
            const int px = i & 63;
            const int l  = i >> 6;           // 0..71 : (c_local, k)
            const int c  = l / 9, k = l - c * 9;
            const float* xp = xb + (size_t)c * HW;
            float s = 0.f;
#pragma unroll
            for (int c2 = 0; c2 < 4; c2++)
                s = fmaf(sWt[(c2 * K + k) * 64 + px],
                         __ldg(xp + sIdx[(c2 * K + k) * 64 + px]), s);
            sS[l * 64 + px] = s;
        }
        __syncthreads();

        const u64* sS64 = (const u64*)sS;
#pragma unroll 4
        for (int l = 0; l < 72; l++) {
            const u64 s = sS64[l * 32 + lane];       // {s_px0, s_px1}
            float2 f = unpack2(s);
            const u64 d0 = dup2(f.x), d1 = dup2(f.y);
            const u64* wp = (const u64*)(sWd + l * 64 + og * 8);
#pragma unroll
            for (int pr = 0; pr < 4; pr++) {
                const u64 wv = wp[pr];               // uniform LDS.64 {w_o, w_o+1}
                ffma2(accA[pr], d0, wv);
                ffma2(accB[pr], d1, wv);
            }
        }
        __syncthreads();
    }

    // epilogue: accA[pr] = {out[px0][co], out[px0][co+1]}, accB for px1
    const int pxg = x0 + 2 * lane;
#pragma unroll
    for (int pr = 0; pr < 4; pr++) {
        const int co = og * 8 + 2 * pr;
        const float b0 = bias[co], b1 = bias[co + 1];
        float2 a = unpack2(accA[pr]);
        float2 bb = unpack2(accB[pr]);
        float2 v0, v1;
        v0.x = lrelu(a.x + b0);  v0.y = lrelu(bb.x + b0);
        v1.x = lrelu(a.y + b1);  v1.y = lrelu(bb.y + b1);
        *(float2*)(out + ((size_t)b * NF + co)     * HW + y * W + pxg) = v0;
        *(float2*)(out + ((size_t)b * NF + co + 1) * HW + y * W + pxg) = v1;
    }
}

// ---------------------------------------------------------------------------
extern "C" void kernel_launch(void* const* d_in, const int* in_sizes, int n_in,
                              void* d_out, int out_size)
{
    const float* nbr   = (const float*)d_in[0];
    const float* ref   = (const float*)d_in[1];
    const float* w1    = (const float*)d_in[2];
    const float* b1    = (const float*)d_in[3];
    const float* w2    = (const float*)d_in[4];
    const float* b2    = (const float*)d_in[5];
    const float* w3    = (const float*)d_in[6];
    const float* b3    = (const float*)d_in[7];
    const float* w_off = (const float*)d_in[8];
    const float* b_off = (const float*)d_in[9];
    const float* w_dcn = (const float*)d_in[10];
    const float* b_dcn = (const float*)d_in[11];

    float* out  = (float*)d_out;
    float* feat = out;                                   // [B,64,H,W]
    float* offs = out + (size_t)BN * NF * HW;            // [B,18,H,W]
    float* msk  = offs + (size_t)BN * 18 * HW;           // [B, 9,H,W]

    float *bufA, *bufB, *wT;
    cudaGetSymbolAddress((void**)&bufA, g_bufA);
    cudaGetSymbolAddress((void**)&bufB, g_bufB);
    cudaGetSymbolAddress((void**)&wT,   g_wT);

    transpose_wdcn_kernel<<<(NF * NF * 9 + 255) / 256, 256>>>(w_dcn, wT);
    conv3x3p_kernel<128, 64, true ><<<dim3(32, 8, 4), 128>>>(nbr, ref, w1, b1, bufA);
    conv3x3p_kernel< 64, 64, false><<<dim3(32, 8, 4), 128>>>(bufA, bufA, w2, b2, bufB);
    conv3x3p_kernel< 64, 64, false><<<dim3(32, 8, 4), 128>>>(bufB, bufB, w3, b3, bufA);
    conv_offset_kernel<<<dim3(64, 3, 4), 128>>>(bufA, w_off, b_off, offs, msk);

    const int dcn_smem = 9216 + 9216 + 18432 + 18432;    // 55296 B
    cudaFuncSetAttribute(dcn_kernel, cudaFuncAttributeMaxDynamicSharedMemorySize, dcn_smem);
    dcn_kernel<<<dim3(2, 128, 4), 256, dcn_smem>>>(nbr, offs, msk, wT, b_dcn, feat);
}